// round 13
// baseline (speedup 1.0000x reference)
#include <cuda_runtime.h>
#include <cuda_bf16.h>
#include <math.h>
#include <stdint.h>

// RGAT: 4x GATv2 over 15552 independent 17-node graphs, C=128.
// Per block: 4 graphs in TWO independent warp-groups (8 warps / 2 graphs each),
// synced by named barriers only -> cross-group phase overlap.
// GEMM core = mma.sync m16n8k16 bf16 split hi/lo, fp32 accum (verified R10 math).

namespace {
constexpr int J   = 17;
constexpr int C   = 128;
constexpr int GPG = 2;                   // graphs per group
constexpr int MROWS_G = GPG * J;         // 34
constexpr int MPAD_G  = 48;              // 3 m-tiles
constexpr int NMT = MPAD_G / 16;         // 3
constexpr int NE  = 64;
constexpr int NTH = 512;
constexpr int GPB = 4;                   // graphs per block (2 groups x 2)
constexpr int NGRAPHS = 15552;
constexpr int NBLOCKS = NGRAPHS / GPB;   // 3888
constexpr int MPADT = 37;                // xlT/xrT row stride (37 mod 32 = 5)
constexpr int AUG = 24576;               // per-group union: Ah(12288)+Al(12288) | xrT(18944)
}

__device__ constexpr int ESRC[NE] = {
  0,0,0,1,1,2,2,3,4,4,5,5,6,7,7,8,8,8,8,9,9,10,11,11,12,12,13,14,14,15,15,16,
  1,4,7,0,2,1,3,2,0,5,4,6,5,0,8,7,9,11,14,8,10,9,8,12,11,13,12,8,15,14,16,15
};
__device__ constexpr int EDST[NE] = {
  1,4,7,0,2,1,3,2,0,5,4,6,5,0,8,7,9,11,14,8,10,9,8,12,11,13,12,8,15,14,16,15,
  0,0,0,1,1,2,2,3,4,4,5,5,6,7,7,8,8,8,8,9,9,10,11,11,12,12,13,14,14,15,15,16
};
__device__ __constant__ int c_esrc[NE] = {
  0,0,0,1,1,2,2,3,4,4,5,5,6,7,7,8,8,8,8,9,9,10,11,11,12,12,13,14,14,15,15,16,
  1,4,7,0,2,1,3,2,0,5,4,6,5,0,8,7,9,11,14,8,10,9,8,12,11,13,12,8,15,14,16,15
};
__device__ __constant__ int c_edst[NE] = {
  1,4,7,0,2,1,3,2,0,5,4,6,5,0,8,7,9,11,14,8,10,9,8,12,11,13,12,8,15,14,16,15,
  0,0,0,1,1,2,2,3,4,4,5,5,6,7,7,8,8,8,8,9,9,10,11,11,12,12,13,14,14,15,15,16
};

struct Smem {
  __nv_bfloat16 Wlh[C*C];     // [k][n] swizzled, 32 KB each (shared, read-only)
  __nv_bfloat16 Wll[C*C];
  __nv_bfloat16 Wrh[C*C];
  __nv_bfloat16 Wrl[C*C];
  char uni[2][AUG];           // per group: Ah @+0, Al @+12288 | xrT @+0
  float xlT[2][C][MPADT];     // per group: 18944 B
  float bl[C], br[C], att[C], bias[C];
  float logit[2][GPG*NE], aw[2][GPG*NE];
  float mx[2][MROWS_G], den[2][MROWS_G];
};

// ---------------- helpers ----------------
__device__ __forceinline__ uint32_t smem_u32(const void* p) {
  uint32_t a;
  asm("{ .reg .u64 t; cvta.to.shared.u64 t, %1; cvt.u32.u64 %0, t; }" : "=r"(a) : "l"(p));
  return a;
}
__device__ __forceinline__ void ldsm4(uint32_t* f, uint32_t a) {
  asm volatile("ldmatrix.sync.aligned.m8n8.x4.shared.b16 {%0,%1,%2,%3}, [%4];"
    : "=r"(f[0]),"=r"(f[1]),"=r"(f[2]),"=r"(f[3]) : "r"(a));
}
__device__ __forceinline__ void ldsm2t(uint32_t* f, uint32_t a) {
  asm volatile("ldmatrix.sync.aligned.m8n8.x2.trans.shared.b16 {%0,%1}, [%2];"
    : "=r"(f[0]),"=r"(f[1]) : "r"(a));
}
__device__ __forceinline__ void mma16816(float* d, const uint32_t* a, const uint32_t* b) {
  asm volatile("mma.sync.aligned.m16n8k16.row.col.f32.bf16.bf16.f32 "
    "{%0,%1,%2,%3}, {%4,%5,%6,%7}, {%8,%9}, {%0,%1,%2,%3};"
    : "+f"(d[0]),"+f"(d[1]),"+f"(d[2]),"+f"(d[3])
    : "r"(a[0]),"r"(a[1]),"r"(a[2]),"r"(a[3]), "r"(b[0]),"r"(b[1]));
}
// A tile byte offset: row m, col k. 256B rows, 16B chunks XOR-swizzled by m&7.
__device__ __forceinline__ uint32_t swzA(int m, int k) {
  return (uint32_t)(m*256 + ((((k>>3) ^ (m&7))<<4) | ((k&7)*2)));
}
__device__ __forceinline__ ushort bf16u(float v) {
  return __bfloat16_as_ushort(__float2bfloat16(v));
}
// named-barrier sync for group's 256 threads (ids 1 and 2; id 0 = __syncthreads)
__device__ __forceinline__ void barg(int g) {
  asm volatile("bar.sync %0, %1;" :: "r"(g + 1), "r"(256) : "memory");
}

__global__ __launch_bounds__(NTH, 1)
void rgat_hmma_kernel(const float* __restrict__ x,
                      const float* __restrict__ ln_gamma,
                      const float* __restrict__ ln_beta,
                      const float* __restrict__ alpha,
                      const float* __restrict__ Wl,
                      const float* __restrict__ bl,
                      const float* __restrict__ Wr,
                      const float* __restrict__ br,
                      const float* __restrict__ att,
                      const float* __restrict__ bias,
                      float* __restrict__ out)
{
  extern __shared__ char raw[];
  uintptr_t pa = ((uintptr_t)raw + 1023) & ~(uintptr_t)1023;
  Smem& s = *reinterpret_cast<Smem*>(pa);

  const int t    = threadIdx.x;
  const int warp = t >> 5;
  const int lane = t & 31;
  const int grp  = warp >> 3;                 // 0 or 1
  const int wg   = warp & 7;                  // warp id within group
  const int tg   = t & 255;                   // thread id within group

  char* Ah_base = s.uni[grp];
  char* Al_base = s.uni[grp] + MPAD_G*C*2;    // +12288
  float (*xrT)[MPADT] = reinterpret_cast<float (*)[MPADT]>(s.uni[grp]);
  float (*xlT)[MPADT] = s.xlT[grp];

  const int node0 = blockIdx.x * (2*MROWS_G) + grp * MROWS_G;
  const float* xblk = x + (size_t)node0 * C;

  // ---- prologue (all 512 threads cooperatively) ----
  for (int i = t; i < 2*AUG/4; i += NTH)
    reinterpret_cast<uint32_t*>(s.uni)[i] = 0u;
  for (int i = t; i < C*C/4; i += NTH) {
    int k = i >> 5, n4 = (i & 31) * 4;
    float4 vl = reinterpret_cast<const float4*>(Wl)[i];
    float4 vr = reinterpret_cast<const float4*>(Wr)[i];
    uint32_t off = (uint32_t)(k*256 + ((((n4>>3) ^ (k&7))<<4) | ((n4&7)*2)));
    ushort h0 = bf16u(vl.x), h1 = bf16u(vl.y), h2 = bf16u(vl.z), h3 = bf16u(vl.w);
    uint2 hp = make_uint2((uint32_t)h0 | ((uint32_t)h1 << 16),
                          (uint32_t)h2 | ((uint32_t)h3 << 16));
    uint2 lp = make_uint2(
      (uint32_t)bf16u(vl.x - __bfloat162float(__ushort_as_bfloat16(h0))) |
      ((uint32_t)bf16u(vl.y - __bfloat162float(__ushort_as_bfloat16(h1))) << 16),
      (uint32_t)bf16u(vl.z - __bfloat162float(__ushort_as_bfloat16(h2))) |
      ((uint32_t)bf16u(vl.w - __bfloat162float(__ushort_as_bfloat16(h3))) << 16));
    *reinterpret_cast<uint2*>(reinterpret_cast<char*>(s.Wlh) + off) = hp;
    *reinterpret_cast<uint2*>(reinterpret_cast<char*>(s.Wll) + off) = lp;
    h0 = bf16u(vr.x); h1 = bf16u(vr.y); h2 = bf16u(vr.z); h3 = bf16u(vr.w);
    hp = make_uint2((uint32_t)h0 | ((uint32_t)h1 << 16),
                    (uint32_t)h2 | ((uint32_t)h3 << 16));
    lp = make_uint2(
      (uint32_t)bf16u(vr.x - __bfloat162float(__ushort_as_bfloat16(h0))) |
      ((uint32_t)bf16u(vr.y - __bfloat162float(__ushort_as_bfloat16(h1))) << 16),
      (uint32_t)bf16u(vr.z - __bfloat162float(__ushort_as_bfloat16(h2))) |
      ((uint32_t)bf16u(vr.w - __bfloat162float(__ushort_as_bfloat16(h3))) << 16));
    *reinterpret_cast<uint2*>(reinterpret_cast<char*>(s.Wrh) + off) = hp;
    *reinterpret_cast<uint2*>(reinterpret_cast<char*>(s.Wrl) + off) = lp;
  }
  for (int i = t; i < C; i += NTH) {
    s.bl[i] = bl[i]; s.br[i] = br[i]; s.att[i] = att[i]; s.bias[i] = bias[i];
  }
  const float sg  = 1.0f / (1.0f + __expf(-alpha[0]));
  const float oms = 1.0f - sg;
  __syncthreads();   // only full-block barrier; groups are independent below

  // ---- LayerNorm -> group's Ah/Al (hi/lo bf16) ----
  for (int r = wg; r < MROWS_G; r += 8) {
    float v0 = xblk[r*C + lane],      v1 = xblk[r*C + lane + 32];
    float v2 = xblk[r*C + lane + 64], v3 = xblk[r*C + lane + 96];
    float sum = v0+v1+v2+v3, sq = v0*v0+v1*v1+v2*v2+v3*v3;
    #pragma unroll
    for (int o = 16; o > 0; o >>= 1) {
      sum += __shfl_xor_sync(0xffffffffu, sum, o);
      sq  += __shfl_xor_sync(0xffffffffu, sq,  o);
    }
    float mu = sum * (1.0f/C);
    float inv = rsqrtf(sq * (1.0f/C) - mu*mu + 1e-5f);
    #pragma unroll
    for (int q = 0; q < 4; ++q) {
      int cc = lane + 32*q;
      float vv = (q==0?v0:q==1?v1:q==2?v2:v3);
      float hval = (vv-mu)*inv*ln_gamma[cc] + ln_beta[cc];
      ushort hi = bf16u(hval);
      *reinterpret_cast<ushort*>(Ah_base + swzA(r, cc)) = hi;
      *reinterpret_cast<ushort*>(Al_base + swzA(r, cc)) =
          bf16u(hval - __bfloat162float(__ushort_as_bfloat16(hi)));
    }
  }

  const uint32_t aAh  = smem_u32(Ah_base), aAl  = smem_u32(Al_base);
  const uint32_t aWlh = smem_u32(s.Wlh), aWll = smem_u32(s.Wll);
  const uint32_t aWrh = smem_u32(s.Wrh), aWrl = smem_u32(s.Wrl);
  // lane decomposition for ldmatrix addressing
  const int rA = lane & 7;
  const int rowOffA = ((lane>>3)&1)*8 + rA;
  const int chOffA  = (lane>>4);
  const int rB  = lane & 7;
  const int miB = (lane>>3)&1;
  const int n0w = wg * 16;                    // this warp's 16 output columns
  const int eM = lane >> 2;
  const int eN = 2*(lane & 3);

  #pragma unroll 1
  for (int layer = 0; layer < 4; ++layer) {
    barg(grp);   // Ah/Al ready (LN or previous aggregation)

    float accL[NMT][2][4];
    float accR[NMT][2][4];
    #pragma unroll
    for (int mt = 0; mt < NMT; ++mt)
      #pragma unroll
      for (int nt = 0; nt < 2; ++nt)
        #pragma unroll
        for (int q = 0; q < 4; ++q) { accL[mt][nt][q] = 0.f; accR[mt][nt][q] = 0.f; }

    #pragma unroll
    for (int ks = 0; ks < 8; ++ks) {
      uint32_t fAh[NMT][4], fAl[NMT][4];
      #pragma unroll
      for (int mt = 0; mt < NMT; ++mt) {
        uint32_t ar = (uint32_t)((mt*16 + rowOffA)*256 + (((2*ks + chOffA) ^ rA)<<4));
        ldsm4(fAh[mt], aAh + ar);
        ldsm4(fAl[mt], aAl + ar);
      }
      #pragma unroll
      for (int nt = 0; nt < 2; ++nt) {
        int n0 = n0w + nt*8;
        uint32_t boff = (uint32_t)((ks*16 + miB*8 + rB)*256 + (((n0>>3) ^ rB)<<4));
        uint32_t bh[2], blo[2];
        ldsm2t(bh,  aWlh + boff);
        ldsm2t(blo, aWll + boff);
        #pragma unroll
        for (int mt = 0; mt < NMT; ++mt) {
          mma16816(accL[mt][nt], fAh[mt], bh);
          mma16816(accL[mt][nt], fAl[mt], bh);
          mma16816(accL[mt][nt], fAh[mt], blo);
        }
        ldsm2t(bh,  aWrh + boff);
        ldsm2t(blo, aWrl + boff);
        #pragma unroll
        for (int mt = 0; mt < NMT; ++mt) {
          mma16816(accR[mt][nt], fAh[mt], bh);
          mma16816(accR[mt][nt], fAl[mt], bh);
          mma16816(accR[mt][nt], fAh[mt], blo);
        }
      }
    }
    barg(grp);   // group's GEMM reads of Ah/Al done before xrT overwrites

    // ---- epilogue: fragments -> xlT / xrT-in-union (+bias) ----
    #pragma unroll
    for (int nt = 0; nt < 2; ++nt) {
      int n0 = n0w + nt*8 + eN;
      float b0 = s.bl[n0], b1 = s.bl[n0+1];
      float c0 = s.br[n0], c1 = s.br[n0+1];
      #pragma unroll
      for (int mt = 0; mt < NMT; ++mt) {
        int m0 = mt*16 + eM;
        if (m0 < MROWS_G) {
          xlT[n0  ][m0] = accL[mt][nt][0] + b0;
          xlT[n0+1][m0] = accL[mt][nt][1] + b1;
          xrT[n0  ][m0] = accR[mt][nt][0] + c0;
          xrT[n0+1][m0] = accR[mt][nt][1] + c1;
        }
        if (m0+8 < MROWS_G) {
          xlT[n0  ][m0+8] = accL[mt][nt][2] + b0;
          xlT[n0+1][m0+8] = accL[mt][nt][3] + b1;
          xrT[n0  ][m0+8] = accR[mt][nt][2] + c0;
          xrT[n0+1][m0+8] = accR[mt][nt][3] + c1;
        }
      }
    }
    barg(grp);

    // ---- edge logits: att . leaky_relu(xl[src] + xr[dst]) ----
    #pragma unroll
    for (int i = 0; i < 16; ++i) {          // 8 warps * 16 = 128 edges (2 graphs)
      int eg = wg + 8*i;
      int gl = eg >> 6, e = eg & 63;
      int gs = gl*J + c_esrc[e];
      int gd = gl*J + c_edst[e];
      float acc = 0.0f;
      #pragma unroll
      for (int q = 0; q < 4; ++q) {
        int cc = lane + 32*q;
        float v = xlT[cc][gs] + xrT[cc][gd];
        v = (v > 0.0f) ? v : 0.2f*v;
        acc += s.att[cc]*v;
      }
      #pragma unroll
      for (int o = 16; o > 0; o >>= 1)
        acc += __shfl_xor_sync(0xffffffffu, acc, o);
      if (lane == 0) s.logit[grp][eg] = acc;
    }
    barg(grp);

    // ---- segment softmax: mx/den (one thread per node) ----
    if (tg < MROWS_G) {
      int gl = tg / J, n = tg - gl * J;
      const float* lg = &s.logit[grp][gl*NE];
      float m = -1e30f;
      #pragma unroll
      for (int e = 0; e < NE; ++e) if (EDST[e] == n) m = fmaxf(m, lg[e]);
      float d = 0.0f;
      #pragma unroll
      for (int e = 0; e < NE; ++e) if (EDST[e] == n) d += __expf(lg[e] - m);
      s.mx[grp][tg] = m; s.den[grp][tg] = d;
    }
    barg(grp);
    if (tg < GPG*NE) {
      int gl = tg >> 6, e = tg & 63;
      int dn = gl*J + c_edst[e];
      s.aw[grp][tg] = __expf(s.logit[grp][tg] - s.mx[grp][dn]) / s.den[grp][dn];
    }
    barg(grp);

    // ---- aggregation + gate (all 256 group threads); layer3 -> out ----
    {
      int gl = tg >> 7, cc = tg & 127;
      float acc[J];
      #pragma unroll
      for (int n = 0; n < J; ++n) acc[n] = s.bias[cc];
      const float* ag = &s.aw[grp][gl*NE];
      #pragma unroll
      for (int e = 0; e < NE; ++e)
        acc[EDST[e]] += ag[e] * xlT[cc][gl*J + ESRC[e]];
      #pragma unroll
      for (int n = 0; n < J; ++n) {
        int r = gl*J + n;
        float v = acc[n];
        float xv = xblk[r*C + cc];
        if (layer > 0) v = oms*v + sg*xv;
        if (layer < 3) {
          ushort hi = bf16u(v);
          *reinterpret_cast<ushort*>(Ah_base + swzA(r, cc)) = hi;
          *reinterpret_cast<ushort*>(Al_base + swzA(r, cc)) =
              bf16u(v - __bfloat162float(__ushort_as_bfloat16(hi)));
        } else {
          out[(size_t)(node0 + r)*C + cc] = xv + v;
        }
      }
    }
  }
}

extern "C" void kernel_launch(void* const* d_in, const int* in_sizes, int n_in,
                              void* d_out, int out_size)
{
  const float* x        = (const float*)d_in[0];
  const float* ln_gamma = (const float*)d_in[1];
  const float* ln_beta  = (const float*)d_in[2];
  const float* alpha    = (const float*)d_in[3];
  const float* Wl       = (const float*)d_in[4];
  const float* bl       = (const float*)d_in[5];
  const float* Wr       = (const float*)d_in[6];
  const float* br       = (const float*)d_in[7];
  const float* att      = (const float*)d_in[8];
  const float* bias     = (const float*)d_in[9];
  (void)in_sizes; (void)n_in; (void)out_size;

  int smem = (int)sizeof(Smem) + 1024;
  (void)cudaFuncSetAttribute(rgat_hmma_kernel,
                             cudaFuncAttributeMaxDynamicSharedMemorySize, smem);
  rgat_hmma_kernel<<<NBLOCKS, NTH, smem>>>(
      x, ln_gamma, ln_beta, alpha, Wl, bl, Wr, br, att, bias, (float*)d_out);
}

// round 14
// speedup vs baseline: 1.0288x; 1.0288x over previous
#include <cuda_runtime.h>
#include <cuda_bf16.h>
#include <math.h>
#include <stdint.h>

// RGAT: 4x GATv2 over 15552 independent 17-node graphs, C=128.
// R14 = R10 structure with 1024 threads (32 warps): GEMM split as
// (2 m-halves x 16 n-groups), same total MMA count, 2x warps for latency hiding.

namespace {
constexpr int J   = 17;
constexpr int C   = 128;
constexpr int GPB = 4;
constexpr int MROWS = GPB * J;           // 68
constexpr int MPAD  = 80;                // MMA M (5 m-tiles)
constexpr int NE  = 64;
constexpr int NTH = 1024;
constexpr int NGRAPHS = 15552;
constexpr int NBLOCKS = NGRAPHS / GPB;   // 3888
constexpr int MPADT = 69;                // xlT/xrT row stride (69 mod 32 = 5, coprime)
constexpr int AUNION = 48 * 1024;        // union: Ah(20480)+Al(20480) | xrT(35328)
}

__device__ constexpr int ESRC[NE] = {
  0,0,0,1,1,2,2,3,4,4,5,5,6,7,7,8,8,8,8,9,9,10,11,11,12,12,13,14,14,15,15,16,
  1,4,7,0,2,1,3,2,0,5,4,6,5,0,8,7,9,11,14,8,10,9,8,12,11,13,12,8,15,14,16,15
};
__device__ constexpr int EDST[NE] = {
  1,4,7,0,2,1,3,2,0,5,4,6,5,0,8,7,9,11,14,8,10,9,8,12,11,13,12,8,15,14,16,15,
  0,0,0,1,1,2,2,3,4,4,5,5,6,7,7,8,8,8,8,9,9,10,11,11,12,12,13,14,14,15,15,16
};
__device__ __constant__ int c_esrc[NE] = {
  0,0,0,1,1,2,2,3,4,4,5,5,6,7,7,8,8,8,8,9,9,10,11,11,12,12,13,14,14,15,15,16,
  1,4,7,0,2,1,3,2,0,5,4,6,5,0,8,7,9,11,14,8,10,9,8,12,11,13,12,8,15,14,16,15
};
__device__ __constant__ int c_edst[NE] = {
  1,4,7,0,2,1,3,2,0,5,4,6,5,0,8,7,9,11,14,8,10,9,8,12,11,13,12,8,15,14,16,15,
  0,0,0,1,1,2,2,3,4,4,5,5,6,7,7,8,8,8,8,9,9,10,11,11,12,12,13,14,14,15,15,16
};

struct Smem {
  __nv_bfloat16 Wlh[C*C];   // [k][n] swizzled, 32 KB each
  __nv_bfloat16 Wll[C*C];
  __nv_bfloat16 Wrh[C*C];
  __nv_bfloat16 Wrl[C*C];
  char uni[AUNION];         // Ah @ +0 (20480), Al @ +20480  |  xrT @ +0 (35328)
  float xlT[C][MPADT];      // 35328
  float bl[C], br[C], att[C], bias[C];
  float logit[GPB*NE], aw[GPB*NE];
  float mx[MROWS], den[MROWS];
};

// ---------------- helpers ----------------
__device__ __forceinline__ uint32_t smem_u32(const void* p) {
  uint32_t a;
  asm("{ .reg .u64 t; cvta.to.shared.u64 t, %1; cvt.u32.u64 %0, t; }" : "=r"(a) : "l"(p));
  return a;
}
__device__ __forceinline__ void ldsm4(uint32_t* f, uint32_t a) {
  asm volatile("ldmatrix.sync.aligned.m8n8.x4.shared.b16 {%0,%1,%2,%3}, [%4];"
    : "=r"(f[0]),"=r"(f[1]),"=r"(f[2]),"=r"(f[3]) : "r"(a));
}
__device__ __forceinline__ void ldsm2t(uint32_t* f, uint32_t a) {
  asm volatile("ldmatrix.sync.aligned.m8n8.x2.trans.shared.b16 {%0,%1}, [%2];"
    : "=r"(f[0]),"=r"(f[1]) : "r"(a));
}
__device__ __forceinline__ void mma16816(float* d, const uint32_t* a, const uint32_t* b) {
  asm volatile("mma.sync.aligned.m16n8k16.row.col.f32.bf16.bf16.f32 "
    "{%0,%1,%2,%3}, {%4,%5,%6,%7}, {%8,%9}, {%0,%1,%2,%3};"
    : "+f"(d[0]),"+f"(d[1]),"+f"(d[2]),"+f"(d[3])
    : "r"(a[0]),"r"(a[1]),"r"(a[2]),"r"(a[3]), "r"(b[0]),"r"(b[1]));
}
// A tile byte offset: row m, col k. 256B rows, 16B chunks XOR-swizzled by m&7.
__device__ __forceinline__ uint32_t swzA(int m, int k) {
  return (uint32_t)(m*256 + ((((k>>3) ^ (m&7))<<4) | ((k&7)*2)));
}
__device__ __forceinline__ ushort bf16u(float v) {
  return __bfloat16_as_ushort(__float2bfloat16(v));
}

__global__ __launch_bounds__(NTH, 1)
void rgat_hmma_kernel(const float* __restrict__ x,
                      const float* __restrict__ ln_gamma,
                      const float* __restrict__ ln_beta,
                      const float* __restrict__ alpha,
                      const float* __restrict__ Wl,
                      const float* __restrict__ bl,
                      const float* __restrict__ Wr,
                      const float* __restrict__ br,
                      const float* __restrict__ att,
                      const float* __restrict__ bias,
                      float* __restrict__ out)
{
  extern __shared__ char raw[];
  uintptr_t pa = ((uintptr_t)raw + 1023) & ~(uintptr_t)1023;
  Smem& s = *reinterpret_cast<Smem*>(pa);

  char* Ah_base = s.uni;
  char* Al_base = s.uni + MPAD*C*2;                    // +20480
  float (*xrT)[MPADT] = reinterpret_cast<float (*)[MPADT]>(s.uni);

  const int t    = threadIdx.x;
  const int warp = t >> 5;
  const int lane = t & 31;
  const int node0 = blockIdx.x * MROWS;
  const float* xblk = x + (size_t)node0 * C;

  // ---- prologue: zero A union, W tiles hi/lo swizzled, vectors ----
  for (int i = t; i < AUNION/4; i += NTH)
    reinterpret_cast<uint32_t*>(s.uni)[i] = 0u;
  for (int i = t; i < C*C/4; i += NTH) {
    int k = i >> 5, n4 = (i & 31) * 4;
    float4 vl = reinterpret_cast<const float4*>(Wl)[i];
    float4 vr = reinterpret_cast<const float4*>(Wr)[i];
    uint32_t off = (uint32_t)(k*256 + ((((n4>>3) ^ (k&7))<<4) | ((n4&7)*2)));
    ushort h0 = bf16u(vl.x), h1 = bf16u(vl.y), h2 = bf16u(vl.z), h3 = bf16u(vl.w);
    uint2 hp = make_uint2((uint32_t)h0 | ((uint32_t)h1 << 16),
                          (uint32_t)h2 | ((uint32_t)h3 << 16));
    uint2 lp = make_uint2(
      (uint32_t)bf16u(vl.x - __bfloat162float(__ushort_as_bfloat16(h0))) |
      ((uint32_t)bf16u(vl.y - __bfloat162float(__ushort_as_bfloat16(h1))) << 16),
      (uint32_t)bf16u(vl.z - __bfloat162float(__ushort_as_bfloat16(h2))) |
      ((uint32_t)bf16u(vl.w - __bfloat162float(__ushort_as_bfloat16(h3))) << 16));
    *reinterpret_cast<uint2*>(reinterpret_cast<char*>(s.Wlh) + off) = hp;
    *reinterpret_cast<uint2*>(reinterpret_cast<char*>(s.Wll) + off) = lp;
    h0 = bf16u(vr.x); h1 = bf16u(vr.y); h2 = bf16u(vr.z); h3 = bf16u(vr.w);
    hp = make_uint2((uint32_t)h0 | ((uint32_t)h1 << 16),
                    (uint32_t)h2 | ((uint32_t)h3 << 16));
    lp = make_uint2(
      (uint32_t)bf16u(vr.x - __bfloat162float(__ushort_as_bfloat16(h0))) |
      ((uint32_t)bf16u(vr.y - __bfloat162float(__ushort_as_bfloat16(h1))) << 16),
      (uint32_t)bf16u(vr.z - __bfloat162float(__ushort_as_bfloat16(h2))) |
      ((uint32_t)bf16u(vr.w - __bfloat162float(__ushort_as_bfloat16(h3))) << 16));
    *reinterpret_cast<uint2*>(reinterpret_cast<char*>(s.Wrh) + off) = hp;
    *reinterpret_cast<uint2*>(reinterpret_cast<char*>(s.Wrl) + off) = lp;
  }
  for (int i = t; i < C; i += NTH) {
    s.bl[i] = bl[i]; s.br[i] = br[i]; s.att[i] = att[i]; s.bias[i] = bias[i];
  }
  const float sg  = 1.0f / (1.0f + __expf(-alpha[0]));
  const float oms = 1.0f - sg;
  __syncthreads();   // zero-fill of union must complete before LN writes

  // ---- LayerNorm -> Ah/Al (hi/lo bf16) ----
  for (int r = warp; r < MROWS; r += 32) {
    float v0 = xblk[r*C + lane],      v1 = xblk[r*C + lane + 32];
    float v2 = xblk[r*C + lane + 64], v3 = xblk[r*C + lane + 96];
    float sum = v0+v1+v2+v3, sq = v0*v0+v1*v1+v2*v2+v3*v3;
    #pragma unroll
    for (int o = 16; o > 0; o >>= 1) {
      sum += __shfl_xor_sync(0xffffffffu, sum, o);
      sq  += __shfl_xor_sync(0xffffffffu, sq,  o);
    }
    float mu = sum * (1.0f/C);
    float inv = rsqrtf(sq * (1.0f/C) - mu*mu + 1e-5f);
    #pragma unroll
    for (int q = 0; q < 4; ++q) {
      int cc = lane + 32*q;
      float vv = (q==0?v0:q==1?v1:q==2?v2:v3);
      float hval = (vv-mu)*inv*ln_gamma[cc] + ln_beta[cc];
      ushort hi = bf16u(hval);
      *reinterpret_cast<ushort*>(Ah_base + swzA(r, cc)) = hi;
      *reinterpret_cast<ushort*>(Al_base + swzA(r, cc)) =
          bf16u(hval - __bfloat162float(__ushort_as_bfloat16(hi)));
    }
  }

  const uint32_t aAh  = smem_u32(Ah_base), aAl  = smem_u32(Al_base);
  const uint32_t aWlh = smem_u32(s.Wlh), aWll = smem_u32(s.Wll);
  const uint32_t aWrh = smem_u32(s.Wrh), aWrl = smem_u32(s.Wrl);
  // lane decomposition for ldmatrix addressing
  const int rA = lane & 7;
  const int rowOffA = ((lane>>3)&1)*8 + rA;   // matrix row offset within m16
  const int chOffA  = (lane>>4);              // k-chunk offset (0/1)
  const int rB  = lane & 7;
  const int miB = (lane>>3)&1;
  // GEMM warp mapping: 2 m-halves x 16 n-groups
  const int mh   = warp >> 4;                 // 0: m-tiles 0-2, 1: m-tiles 3-4
  const int n0w  = (warp & 15) * 8;           // this warp's 8 output columns
  const int tb3  = mh * 3;                    // first m-tile index (0 or 3)
  const int eM = lane >> 2;                   // epilogue lane mapping
  const int eN = 2*(lane & 3);

  #pragma unroll 1
  for (int layer = 0; layer < 4; ++layer) {
    __syncthreads();   // Ah/Al ready (LN or previous aggregation)

    float accL[3][4];
    float accR[3][4];
    #pragma unroll
    for (int mt = 0; mt < 3; ++mt)
      #pragma unroll
      for (int q = 0; q < 4; ++q) { accL[mt][q] = 0.f; accR[mt][q] = 0.f; }

    #pragma unroll
    for (int ks = 0; ks < 8; ++ks) {
      uint32_t fAh[3][4], fAl[3][4];
      #pragma unroll
      for (int mt = 0; mt < 3; ++mt) {
        if (mt < 2 || mh == 0) {     // mh=1 has only 2 m-tiles (3,4)
          uint32_t ar = (uint32_t)(((tb3 + mt)*16 + rowOffA)*256 +
                                   (((2*ks + chOffA) ^ rA)<<4));
          ldsm4(fAh[mt], aAh + ar);
          ldsm4(fAl[mt], aAl + ar);
        }
      }
      uint32_t boff = (uint32_t)((ks*16 + miB*8 + rB)*256 + (((n0w>>3) ^ rB)<<4));
      uint32_t bh[2], blo[2];
      ldsm2t(bh,  aWlh + boff);
      ldsm2t(blo, aWll + boff);
      #pragma unroll
      for (int mt = 0; mt < 3; ++mt) {
        if (mt < 2 || mh == 0) {
          mma16816(accL[mt], fAh[mt], bh);
          mma16816(accL[mt], fAl[mt], bh);
          mma16816(accL[mt], fAh[mt], blo);
        }
      }
      ldsm2t(bh,  aWrh + boff);
      ldsm2t(blo, aWrl + boff);
      #pragma unroll
      for (int mt = 0; mt < 3; ++mt) {
        if (mt < 2 || mh == 0) {
          mma16816(accR[mt], fAh[mt], bh);
          mma16816(accR[mt], fAl[mt], bh);
          mma16816(accR[mt], fAh[mt], blo);
        }
      }
    }
    __syncthreads();   // all GEMM reads of Ah/Al done before xrT overwrites them

    // ---- epilogue: fragments -> xlT / xrT-in-union (+bias) ----
    {
      int n0 = n0w + eN;
      float b0 = s.bl[n0], b1 = s.bl[n0+1];
      float c0 = s.br[n0], c1 = s.br[n0+1];
      #pragma unroll
      for (int mt = 0; mt < 3; ++mt) {
        if (mt < 2 || mh == 0) {
          int m0 = (tb3 + mt)*16 + eM;
          if (m0 < MROWS) {
            s.xlT[n0  ][m0] = accL[mt][0] + b0;
            s.xlT[n0+1][m0] = accL[mt][1] + b1;
            xrT[n0  ][m0] = accR[mt][0] + c0;
            xrT[n0+1][m0] = accR[mt][1] + c1;
          }
          if (m0+8 < MROWS) {
            s.xlT[n0  ][m0+8] = accL[mt][2] + b0;
            s.xlT[n0+1][m0+8] = accL[mt][3] + b1;
            xrT[n0  ][m0+8] = accR[mt][2] + c0;
            xrT[n0+1][m0+8] = accR[mt][3] + c1;
          }
        }
      }
    }
    __syncthreads();

    // ---- edge logits: att . leaky_relu(xl[src] + xr[dst]) ----
    #pragma unroll
    for (int i = 0; i < 8; ++i) {          // 32 warps * 8 = 256 edges
      int eg = warp + 32*i;
      int g = eg >> 6, e = eg & 63;
      int gs = g*J + c_esrc[e];
      int gd = g*J + c_edst[e];
      float acc = 0.0f;
      #pragma unroll
      for (int q = 0; q < 4; ++q) {
        int cc = lane + 32*q;
        float v = s.xlT[cc][gs] + xrT[cc][gd];
        v = (v > 0.0f) ? v : 0.2f*v;
        acc += s.att[cc]*v;
      }
      #pragma unroll
      for (int o = 16; o > 0; o >>= 1)
        acc += __shfl_xor_sync(0xffffffffu, acc, o);
      if (lane == 0) s.logit[eg] = acc;
    }
    __syncthreads();

    // ---- segment softmax ----
    if (t < MROWS) {
      int g = t / J, n = t - (t / J) * J;
      const float* lg = &s.logit[g*NE];
      float m = -1e30f;
      #pragma unroll
      for (int e = 0; e < NE; ++e) if (EDST[e] == n) m = fmaxf(m, lg[e]);
      float d = 0.0f;
      #pragma unroll
      for (int e = 0; e < NE; ++e) if (EDST[e] == n) d += __expf(lg[e] - m);
      s.mx[t] = m; s.den[t] = d;
    }
    __syncthreads();
    if (t < GPB*NE) {
      int g = t >> 6, e = t & 63;
      int dn = g*J + c_edst[e];
      s.aw[t] = __expf(s.logit[t] - s.mx[dn]) / s.den[dn];
    }
    __syncthreads();

    // ---- aggregation + gate (512 active threads); layer3 -> out = x + h ----
    if (t < GPB*C) {
      int g = t >> 7, cc = t & 127;
      float acc[J];
      #pragma unroll
      for (int n = 0; n < J; ++n) acc[n] = s.bias[cc];
      const float* ag = &s.aw[g*NE];
      #pragma unroll
      for (int e = 0; e < NE; ++e)
        acc[EDST[e]] += ag[e] * s.xlT[cc][g*J + ESRC[e]];
      #pragma unroll
      for (int n = 0; n < J; ++n) {
        int r = g*J + n;
        float v = acc[n];
        float xv = xblk[r*C + cc];
        if (layer > 0) v = oms*v + sg*xv;
        if (layer < 3) {
          ushort hi = bf16u(v);
          *reinterpret_cast<ushort*>(Ah_base + swzA(r, cc)) = hi;
          *reinterpret_cast<ushort*>(Al_base + swzA(r, cc)) =
              bf16u(v - __bfloat162float(__ushort_as_bfloat16(hi)));
        } else {
          out[(size_t)(node0 + r)*C + cc] = xv + v;
        }
      }
    }
  }
}

extern "C" void kernel_launch(void* const* d_in, const int* in_sizes, int n_in,
                              void* d_out, int out_size)
{
  const float* x        = (const float*)d_in[0];
  const float* ln_gamma = (const float*)d_in[1];
  const float* ln_beta  = (const float*)d_in[2];
  const float* alpha    = (const float*)d_in[3];
  const float* Wl       = (const float*)d_in[4];
  const float* bl       = (const float*)d_in[5];
  const float* Wr       = (const float*)d_in[6];
  const float* br       = (const float*)d_in[7];
  const float* att      = (const float*)d_in[8];
  const float* bias     = (const float*)d_in[9];
  (void)in_sizes; (void)n_in; (void)out_size;

  int smem = (int)sizeof(Smem) + 1024;
  (void)cudaFuncSetAttribute(rgat_hmma_kernel,
                             cudaFuncAttributeMaxDynamicSharedMemorySize, smem);
  rgat_hmma_kernel<<<NBLOCKS, NTH, smem>>>(
      x, ln_gamma, ln_beta, alpha, Wl, bl, Wr, br, att, bias, (float*)d_out);
}

// round 15
// speedup vs baseline: 1.0931x; 1.0625x over previous
#include <cuda_runtime.h>
#include <cuda_bf16.h>
#include <math.h>
#include <stdint.h>

// RGAT: 4x GATv2 over 15552 independent 17-node graphs, C=128.
// R15 = R10 + aggregation-as-MMA: out = P @ xl per graph (P = dense 17x17
// attention matrix, bf16 hi/lo split), xl/xr stored as bf16 hi/lo A-layout
// tiles. GEMM1 (h@Wl, h@Wr) identical to R10.

namespace {
constexpr int J   = 17;
constexpr int C   = 128;
constexpr int GPB = 4;
constexpr int MROWS = GPB * J;           // 68
constexpr int MPAD  = 80;                // GEMM1 M (5 m-tiles)
constexpr int NMT = MPAD / 16;           // 5
constexpr int NE  = 64;
constexpr int NTH = 512;
constexpr int NGRAPHS = 15552;
constexpr int NBLOCKS = NGRAPHS / GPB;   // 3888
constexpr int TILE_B = MPAD * C * 2;     // 20480 bytes per bf16 tile
constexpr int PG_B  = 32 * 64;           // 2048 bytes per graph P tile (32 rows x 64B)
constexpr int P_B   = GPB * PG_B;        // 8192 per hi/lo
}

__device__ __constant__ int c_esrc[NE] = {
  0,0,0,1,1,2,2,3,4,4,5,5,6,7,7,8,8,8,8,9,9,10,11,11,12,12,13,14,14,15,15,16,
  1,4,7,0,2,1,3,2,0,5,4,6,5,0,8,7,9,11,14,8,10,9,8,12,11,13,12,8,15,14,16,15
};
__device__ __constant__ int c_edst[NE] = {
  1,4,7,0,2,1,3,2,0,5,4,6,5,0,8,7,9,11,14,8,10,9,8,12,11,13,12,8,15,14,16,15,
  0,0,0,1,1,2,2,3,4,4,5,5,6,7,7,8,8,8,8,9,9,10,11,11,12,12,13,14,14,15,15,16
};
__device__ constexpr int EDST[NE] = {
  1,4,7,0,2,1,3,2,0,5,4,6,5,0,8,7,9,11,14,8,10,9,8,12,11,13,12,8,15,14,16,15,
  0,0,0,1,1,2,2,3,4,4,5,5,6,7,7,8,8,8,8,9,9,10,11,11,12,12,13,14,14,15,15,16
};

struct Smem {
  __nv_bfloat16 Wlh[C*C];   // [k][n] swizzled, 32 KB each
  __nv_bfloat16 Wll[C*C];
  __nv_bfloat16 Wrh[C*C];
  __nv_bfloat16 Wrl[C*C];
  char uni1[2*TILE_B];      // h hi/lo tiles  <->  xl hi/lo tiles (A-layout)
  char uni2[2*TILE_B];      // xr hi/lo tiles  |  P hi/lo (16384) aliased
  float bl[C], br[C], att[C], bias[C];
  float logit[GPB*NE];
  float mx[MROWS], den[MROWS];
};

// ---------------- helpers ----------------
__device__ __forceinline__ uint32_t smem_u32(const void* p) {
  uint32_t a;
  asm("{ .reg .u64 t; cvta.to.shared.u64 t, %1; cvt.u32.u64 %0, t; }" : "=r"(a) : "l"(p));
  return a;
}
__device__ __forceinline__ void ldsm4(uint32_t* f, uint32_t a) {
  asm volatile("ldmatrix.sync.aligned.m8n8.x4.shared.b16 {%0,%1,%2,%3}, [%4];"
    : "=r"(f[0]),"=r"(f[1]),"=r"(f[2]),"=r"(f[3]) : "r"(a));
}
__device__ __forceinline__ void ldsm2t(uint32_t* f, uint32_t a) {
  asm volatile("ldmatrix.sync.aligned.m8n8.x2.trans.shared.b16 {%0,%1}, [%2];"
    : "=r"(f[0]),"=r"(f[1]) : "r"(a));
}
__device__ __forceinline__ void mma16816(float* d, const uint32_t* a, const uint32_t* b) {
  asm volatile("mma.sync.aligned.m16n8k16.row.col.f32.bf16.bf16.f32 "
    "{%0,%1,%2,%3}, {%4,%5,%6,%7}, {%8,%9}, {%0,%1,%2,%3};"
    : "+f"(d[0]),"+f"(d[1]),"+f"(d[2]),"+f"(d[3])
    : "r"(a[0]),"r"(a[1]),"r"(a[2]),"r"(a[3]), "r"(b[0]),"r"(b[1]));
}
// A tile byte offset: row m, col k. 256B rows, 16B chunks XOR-swizzled by m&7.
__device__ __forceinline__ uint32_t swzA(int m, int k) {
  return (uint32_t)(m*256 + ((((k>>3) ^ (m&7))<<4) | ((k&7)*2)));
}
__device__ __forceinline__ ushort bf16u(float v) {
  return __bfloat16_as_ushort(__float2bfloat16(v));
}
__device__ __forceinline__ float2 bf2f(uint32_t u) {
  __nv_bfloat162 b = *reinterpret_cast<__nv_bfloat162*>(&u);
  return __bfloat1622float2(b);
}
// store hi/lo pair of (v0,v1) at tile base + off (hi) and base + TILE_B (lo)
__device__ __forceinline__ void store_split(char* base, uint32_t off, float v0, float v1) {
  __nv_bfloat16 h0 = __float2bfloat16(v0);
  __nv_bfloat16 h1 = __float2bfloat16(v1);
  __nv_bfloat162 hp = __halves2bfloat162(h0, h1);
  __nv_bfloat162 lp = __halves2bfloat162(
      __float2bfloat16(v0 - __bfloat162float(h0)),
      __float2bfloat16(v1 - __bfloat162float(h1)));
  *reinterpret_cast<uint32_t*>(base + off)          = *reinterpret_cast<uint32_t*>(&hp);
  *reinterpret_cast<uint32_t*>(base + TILE_B + off) = *reinterpret_cast<uint32_t*>(&lp);
}

__global__ __launch_bounds__(NTH, 1)
void rgat_hmma_kernel(const float* __restrict__ x,
                      const float* __restrict__ ln_gamma,
                      const float* __restrict__ ln_beta,
                      const float* __restrict__ alpha,
                      const float* __restrict__ Wl,
                      const float* __restrict__ bl,
                      const float* __restrict__ Wr,
                      const float* __restrict__ br,
                      const float* __restrict__ att,
                      const float* __restrict__ bias,
                      float* __restrict__ out)
{
  extern __shared__ char raw[];
  uintptr_t pa = ((uintptr_t)raw + 1023) & ~(uintptr_t)1023;
  Smem& s = *reinterpret_cast<Smem*>(pa);

  char* H  = s.uni1;                 // h / xl hi tile (lo at +TILE_B)
  char* XR = s.uni2;                 // xr hi tile (lo at +TILE_B)
  char* Ph = s.uni2;                 // P hi (aliases dead xr), lo at +P_B
  char* Pl = s.uni2 + P_B;

  const int t    = threadIdx.x;
  const int warp = t >> 5;
  const int lane = t & 31;
  const int node0 = blockIdx.x * MROWS;
  const float* xblk = x + (size_t)node0 * C;

  // ---- prologue: W tiles hi/lo swizzled, vectors ----
  for (int i = t; i < C*C/4; i += NTH) {
    int k = i >> 5, n4 = (i & 31) * 4;
    float4 vl = reinterpret_cast<const float4*>(Wl)[i];
    float4 vr = reinterpret_cast<const float4*>(Wr)[i];
    uint32_t off = (uint32_t)(k*256 + ((((n4>>3) ^ (k&7))<<4) | ((n4&7)*2)));
    ushort h0 = bf16u(vl.x), h1 = bf16u(vl.y), h2 = bf16u(vl.z), h3 = bf16u(vl.w);
    uint2 hp = make_uint2((uint32_t)h0 | ((uint32_t)h1 << 16),
                          (uint32_t)h2 | ((uint32_t)h3 << 16));
    uint2 lp = make_uint2(
      (uint32_t)bf16u(vl.x - __bfloat162float(__ushort_as_bfloat16(h0))) |
      ((uint32_t)bf16u(vl.y - __bfloat162float(__ushort_as_bfloat16(h1))) << 16),
      (uint32_t)bf16u(vl.z - __bfloat162float(__ushort_as_bfloat16(h2))) |
      ((uint32_t)bf16u(vl.w - __bfloat162float(__ushort_as_bfloat16(h3))) << 16));
    *reinterpret_cast<uint2*>(reinterpret_cast<char*>(s.Wlh) + off) = hp;
    *reinterpret_cast<uint2*>(reinterpret_cast<char*>(s.Wll) + off) = lp;
    h0 = bf16u(vr.x); h1 = bf16u(vr.y); h2 = bf16u(vr.z); h3 = bf16u(vr.w);
    hp = make_uint2((uint32_t)h0 | ((uint32_t)h1 << 16),
                    (uint32_t)h2 | ((uint32_t)h3 << 16));
    lp = make_uint2(
      (uint32_t)bf16u(vr.x - __bfloat162float(__ushort_as_bfloat16(h0))) |
      ((uint32_t)bf16u(vr.y - __bfloat162float(__ushort_as_bfloat16(h1))) << 16),
      (uint32_t)bf16u(vr.z - __bfloat162float(__ushort_as_bfloat16(h2))) |
      ((uint32_t)bf16u(vr.w - __bfloat162float(__ushort_as_bfloat16(h3))) << 16));
    *reinterpret_cast<uint2*>(reinterpret_cast<char*>(s.Wrh) + off) = hp;
    *reinterpret_cast<uint2*>(reinterpret_cast<char*>(s.Wrl) + off) = lp;
  }
  for (int i = t; i < C; i += NTH) {
    s.bl[i] = bl[i]; s.br[i] = br[i]; s.att[i] = att[i]; s.bias[i] = bias[i];
  }
  const float sg  = 1.0f / (1.0f + __expf(-alpha[0]));
  const float oms = 1.0f - sg;

  // ---- LayerNorm -> h hi/lo tiles ----
  for (int r = warp; r < MROWS; r += 16) {
    float v0 = xblk[r*C + lane],      v1 = xblk[r*C + lane + 32];
    float v2 = xblk[r*C + lane + 64], v3 = xblk[r*C + lane + 96];
    float sum = v0+v1+v2+v3, sq = v0*v0+v1*v1+v2*v2+v3*v3;
    #pragma unroll
    for (int o = 16; o > 0; o >>= 1) {
      sum += __shfl_xor_sync(0xffffffffu, sum, o);
      sq  += __shfl_xor_sync(0xffffffffu, sq,  o);
    }
    float mu = sum * (1.0f/C);
    float inv = rsqrtf(sq * (1.0f/C) - mu*mu + 1e-5f);
    #pragma unroll
    for (int q = 0; q < 4; ++q) {
      int cc = lane + 32*q;
      float vv = (q==0?v0:q==1?v1:q==2?v2:v3);
      float hval = (vv-mu)*inv*ln_gamma[cc] + ln_beta[cc];
      __nv_bfloat16 hi = __float2bfloat16(hval);
      *reinterpret_cast<ushort*>(H + swzA(r, cc)) = __bfloat16_as_ushort(hi);
      *reinterpret_cast<ushort*>(H + TILE_B + swzA(r, cc)) =
          bf16u(hval - __bfloat162float(hi));
    }
  }
  __syncthreads();   // also covers prologue vector stores

  const uint32_t aH   = smem_u32(H);
  const uint32_t aWlh = smem_u32(s.Wlh), aWll = smem_u32(s.Wll);
  const uint32_t aWrh = smem_u32(s.Wrh), aWrl = smem_u32(s.Wrl);
  const uint32_t aXR  = smem_u32(XR);
  const uint32_t aPh  = smem_u32(Ph), aPl = smem_u32(Pl);
  // lane decomposition for ldmatrix addressing
  const int rA = lane & 7;
  const int rowOffA = ((lane>>3)&1)*8 + rA;   // matrix row offset within m16
  const int chOffA  = (lane>>4);              // k-chunk offset (0/1)
  const int rB  = lane & 7;
  const int miB = (lane>>3)&1;
  const int n0w = warp * 8;                   // this warp's 8 output columns
  const int eM = lane >> 2;                   // epilogue lane mapping
  const int eN = 2*(lane & 3);
  // per-thread preloads
  const float2 blv   = make_float2(s.bl[n0w+eN],   s.bl[n0w+eN+1]);
  const float2 brv   = make_float2(s.br[n0w+eN],   s.br[n0w+eN+1]);
  const float2 biasv = make_float2(s.bias[n0w+eN], s.bias[n0w+eN+1]);
  const float4 att4  = *reinterpret_cast<const float4*>(&s.att[lane*4]);
  // edge-phase lane addressing: 4 channels c0=lane*4
  const uint32_t eChunkOff = (uint32_t)(((lane>>1)<<4) /*chunk<<4 pre-XOR*/);
  const uint32_t eByte = (uint32_t)((lane&1)*8);

  #pragma unroll 1
  for (int layer = 0; layer < 4; ++layer) {
    // ================= GEMM1: xl = h@Wl+bl, xr = h@Wr+br =================
    float accL[NMT][4];
    float accR[NMT][4];
    #pragma unroll
    for (int mt = 0; mt < NMT; ++mt)
      #pragma unroll
      for (int q = 0; q < 4; ++q) { accL[mt][q] = 0.f; accR[mt][q] = 0.f; }

    #pragma unroll
    for (int ks = 0; ks < 8; ++ks) {
      uint32_t fAh[NMT][4], fAl[NMT][4];
      #pragma unroll
      for (int mt = 0; mt < NMT; ++mt) {
        uint32_t ar = (uint32_t)((mt*16 + rowOffA)*256 + (((2*ks + chOffA) ^ rA)<<4));
        ldsm4(fAh[mt], aH + ar);
        ldsm4(fAl[mt], aH + TILE_B + ar);
      }
      uint32_t boff = (uint32_t)((ks*16 + miB*8 + rB)*256 + (((n0w>>3) ^ rB)<<4));
      uint32_t bh[2], blo[2];
      ldsm2t(bh,  aWlh + boff);
      ldsm2t(blo, aWll + boff);
      #pragma unroll
      for (int mt = 0; mt < NMT; ++mt) {
        mma16816(accL[mt], fAh[mt], bh);
        mma16816(accL[mt], fAl[mt], bh);
        mma16816(accL[mt], fAh[mt], blo);
      }
      ldsm2t(bh,  aWrh + boff);
      ldsm2t(blo, aWrl + boff);
      #pragma unroll
      for (int mt = 0; mt < NMT; ++mt) {
        mma16816(accR[mt], fAh[mt], bh);
        mma16816(accR[mt], fAl[mt], bh);
        mma16816(accR[mt], fAh[mt], blo);
      }
    }
    __syncthreads();   // all reads of h done; uni1/uni2 reusable

    // ---- epilogue1: xl -> uni1 tiles (over h), xr -> uni2 tiles ----
    {
      int n0 = n0w + eN;
      #pragma unroll
      for (int mt = 0; mt < NMT; ++mt) {
        int m0 = mt*16 + eM;
        if (m0 < MROWS) {
          uint32_t off = swzA(m0, n0);
          store_split(H,  off, accL[mt][0] + blv.x, accL[mt][1] + blv.y);
          store_split(XR, off, accR[mt][0] + brv.x, accR[mt][1] + brv.y);
        }
        if (m0+8 < MROWS) {
          uint32_t off = swzA(m0+8, n0);
          store_split(H,  off, accL[mt][2] + blv.x, accL[mt][3] + blv.y);
          store_split(XR, off, accR[mt][2] + brv.x, accR[mt][3] + brv.y);
        }
      }
    }
    __syncthreads();

    // ---- edge logits: att . leaky_relu(xl[src] + xr[dst]) ----
    #pragma unroll
    for (int i = 0; i < 16; ++i) {          // 16 warps * 16 = 256 edges
      int eg = warp + 16*i;
      int g = eg >> 6, e = eg & 63;
      int gs = g*J + c_esrc[e];
      int gd = g*J + c_edst[e];
      uint32_t offS = (uint32_t)(gs*256) + ((eChunkOff ^ ((uint32_t)(gs&7)<<4))) + eByte;
      uint32_t offD = (uint32_t)(gd*256) + ((eChunkOff ^ ((uint32_t)(gd&7)<<4))) + eByte;
      uint2 lh = *reinterpret_cast<const uint2*>(H + offS);
      uint2 ll = *reinterpret_cast<const uint2*>(H + TILE_B + offS);
      uint2 rh = *reinterpret_cast<const uint2*>(XR + offD);
      uint2 rl = *reinterpret_cast<const uint2*>(XR + TILE_B + offD);
      float2 xl01 = bf2f(lh.x), xl23 = bf2f(lh.y);
      float2 l01  = bf2f(ll.x), l23  = bf2f(ll.y);
      float2 xr01 = bf2f(rh.x), xr23 = bf2f(rh.y);
      float2 r01  = bf2f(rl.x), r23  = bf2f(rl.y);
      float v0 = xl01.x + l01.x + xr01.x + r01.x;
      float v1 = xl01.y + l01.y + xr01.y + r01.y;
      float v2 = xl23.x + l23.x + xr23.x + r23.x;
      float v3 = xl23.y + l23.y + xr23.y + r23.y;
      v0 = (v0 > 0.f) ? v0 : 0.2f*v0;
      v1 = (v1 > 0.f) ? v1 : 0.2f*v1;
      v2 = (v2 > 0.f) ? v2 : 0.2f*v2;
      v3 = (v3 > 0.f) ? v3 : 0.2f*v3;
      float acc = att4.x*v0 + att4.y*v1 + att4.z*v2 + att4.w*v3;
      #pragma unroll
      for (int o = 16; o > 0; o >>= 1)
        acc += __shfl_xor_sync(0xffffffffu, acc, o);
      if (lane == 0) s.logit[eg] = acc;
    }
    __syncthreads();

    // ---- segment softmax mx/den (t<68) || zero P tiles (t>=128) ----
    if (t < MROWS) {
      int g = t / J, n = t - (t / J) * J;
      const float* lg = &s.logit[g*NE];
      float m = -1e30f;
      #pragma unroll
      for (int e = 0; e < NE; ++e) if (EDST[e] == n) m = fmaxf(m, lg[e]);
      float d = 0.0f;
      #pragma unroll
      for (int e = 0; e < NE; ++e) if (EDST[e] == n) d += __expf(lg[e] - m);
      s.mx[t] = m; s.den[t] = d;
    } else if (t >= 128) {
      for (int i = t - 128; i < 2*P_B/4; i += NTH - 128)
        reinterpret_cast<uint32_t*>(Ph)[i] = 0u;
    }
    __syncthreads();

    // ---- P scatter: P[g][d][s] = 2*exp(logit-mx)/den (dup writes identical) ----
    if (t < GPB*NE) {
      int g = t >> 6, e = t & 63;
      int d = c_edst[e], sn = c_esrc[e];
      int dn = g*J + d;
      float a2 = 2.0f * __expf(s.logit[t] - s.mx[dn]) / s.den[dn];
      __nv_bfloat16 hi = __float2bfloat16(a2);
      uint32_t off = (uint32_t)(g*PG_B + d*64 + ((((sn>>3) ^ (d&3))<<4) | ((sn&7)*2)));
      *reinterpret_cast<ushort*>(Ph + off) = __bfloat16_as_ushort(hi);
      *reinterpret_cast<ushort*>(Pl + off) =
          bf16u(a2 - __bfloat162float(hi));
    }
    __syncthreads();

    // ================= MMA2: out_g = P_g @ xl_g =================
    float accD[GPB][2][4];
    #pragma unroll
    for (int g = 0; g < GPB; ++g)
      #pragma unroll
      for (int mt = 0; mt < 2; ++mt)
        #pragma unroll
        for (int q = 0; q < 4; ++q) accD[g][mt][q] = 0.f;

    #pragma unroll
    for (int g = 0; g < GPB; ++g) {
      uint32_t pg = (uint32_t)(g * PG_B);
      #pragma unroll
      for (int ks = 0; ks < 2; ++ks) {
        // B: xl rows g*17 + ks*16 + ...
        int krow = g*J + ks*16 + miB*8 + rB;
        uint32_t boff = (uint32_t)(krow*256 + (((n0w>>3) ^ (krow&7))<<4));
        uint32_t bh[2], blo[2];
        ldsm2t(bh,  aH + boff);
        ldsm2t(blo, aH + TILE_B + boff);
        #pragma unroll
        for (int mt = 0; mt < 2; ++mt) {
          uint32_t ar = pg + (uint32_t)((mt*16 + rowOffA)*64 +
                        (((2*ks + chOffA) ^ (rowOffA&3))<<4));
          uint32_t fPh[4], fPl[4];
          ldsm4(fPh, aPh + ar);
          ldsm4(fPl, aPl + ar);
          mma16816(accD[g][mt], fPh, bh);
          mma16816(accD[g][mt], fPh, blo);
          mma16816(accD[g][mt], fPl, bh);
        }
      }
    }
    __syncthreads();   // all MMA2 reads done before h/out writes reuse uni1

    // ---- epilogue2: h = gate(P@xl + bias); layer3 -> out = x + h ----
    #pragma unroll
    for (int g = 0; g < GPB; ++g) {
      #pragma unroll
      for (int mt = 0; mt < 2; ++mt) {
        #pragma unroll
        for (int half = 0; half < 2; ++half) {
          int n = mt*16 + eM + half*8;          // graph-local dst node
          if (n < J) {
            int r = g*J + n;
            float v0 = accD[g][mt][2*half  ] + biasv.x;
            float v1 = accD[g][mt][2*half+1] + biasv.y;
            int cc = n0w + eN;
            float xv0 = xblk[r*C + cc], xv1 = xblk[r*C + cc + 1];
            if (layer > 0) { v0 = oms*v0 + sg*xv0; v1 = oms*v1 + sg*xv1; }
            if (layer < 3) {
              store_split(H, swzA(r, cc), v0, v1);
            } else {
              out[(size_t)(node0 + r)*C + cc    ] = xv0 + v0;
              out[(size_t)(node0 + r)*C + cc + 1] = xv1 + v1;
            }
          }
        }
      }
    }
    __syncthreads();   // h complete before next layer's GEMM1
  }
}

extern "C" void kernel_launch(void* const* d_in, const int* in_sizes, int n_in,
                              void* d_out, int out_size)
{
  const float* x        = (const float*)d_in[0];
  const float* ln_gamma = (const float*)d_in[1];
  const float* ln_beta  = (const float*)d_in[2];
  const float* alpha    = (const float*)d_in[3];
  const float* Wl       = (const float*)d_in[4];
  const float* bl       = (const float*)d_in[5];
  const float* Wr       = (const float*)d_in[6];
  const float* br       = (const float*)d_in[7];
  const float* att      = (const float*)d_in[8];
  const float* bias     = (const float*)d_in[9];
  (void)in_sizes; (void)n_in; (void)out_size;

  int smem = (int)sizeof(Smem) + 1024;
  (void)cudaFuncSetAttribute(rgat_hmma_kernel,
                             cudaFuncAttributeMaxDynamicSharedMemorySize, smem);
  rgat_hmma_kernel<<<NBLOCKS, NTH, smem>>>(
      x, ln_gamma, ln_beta, alpha, Wl, bl, Wr, br, att, bias, (float*)d_out);
}

// round 16
// speedup vs baseline: 1.5467x; 1.4149x over previous
#include <cuda_runtime.h>
#include <cuda_bf16.h>
#include <math.h>
#include <stdint.h>

// RGAT: 4x GATv2 over 15552 independent 17-node graphs, C=128.
// R16 = R10 + unique-edge dedup: the 64-edge list is each directed edge twice
// with identical logits, and the factor-2 cancels in softmax -> run the whole
// attention pipeline on the 32 unique edges. GEMM identical to R10.

namespace {
constexpr int J   = 17;
constexpr int C   = 128;
constexpr int GPB = 4;
constexpr int MROWS = GPB * J;           // 68
constexpr int MPAD  = 80;                // MMA M (5 m-tiles)
constexpr int NMT = MPAD / 16;           // 5
constexpr int NEU = 32;                  // unique directed edges per graph
constexpr int NTH = 512;
constexpr int NGRAPHS = 15552;
constexpr int NBLOCKS = NGRAPHS / GPB;   // 3888
constexpr int MPADT = 69;                // xlT/xrT row stride (69 mod 32 = 5)
constexpr int AUNION = 48 * 1024;        // union: Ah(20480)+Al(20480) | xrT(35328)
}

// 32 unique directed edges (the base list; it is closed under reversal).
__device__ constexpr int ESRC[NEU] = {
  0,0,0,1,1,2,2,3,4,4,5,5,6,7,7,8,8,8,8,9,9,10,11,11,12,12,13,14,14,15,15,16
};
__device__ constexpr int EDST[NEU] = {
  1,4,7,0,2,1,3,2,0,5,4,6,5,0,8,7,9,11,14,8,10,9,8,12,11,13,12,8,15,14,16,15
};
__device__ __constant__ int c_esrc[NEU] = {
  0,0,0,1,1,2,2,3,4,4,5,5,6,7,7,8,8,8,8,9,9,10,11,11,12,12,13,14,14,15,15,16
};
__device__ __constant__ int c_edst[NEU] = {
  1,4,7,0,2,1,3,2,0,5,4,6,5,0,8,7,9,11,14,8,10,9,8,12,11,13,12,8,15,14,16,15
};

struct Smem {
  __nv_bfloat16 Wlh[C*C];   // [k][n] swizzled, 32 KB each
  __nv_bfloat16 Wll[C*C];
  __nv_bfloat16 Wrh[C*C];
  __nv_bfloat16 Wrl[C*C];
  char uni[AUNION];         // Ah @ +0 (20480), Al @ +20480  |  xrT @ +0 (35328)
  float xlT[C][MPADT];      // 35328
  float bl[C], br[C], att[C], bias[C];
  float logit[GPB*NEU], aw[GPB*NEU];
  float mx[MROWS], den[MROWS];
};

// ---------------- helpers ----------------
__device__ __forceinline__ uint32_t smem_u32(const void* p) {
  uint32_t a;
  asm("{ .reg .u64 t; cvta.to.shared.u64 t, %1; cvt.u32.u64 %0, t; }" : "=r"(a) : "l"(p));
  return a;
}
__device__ __forceinline__ void ldsm4(uint32_t* f, uint32_t a) {
  asm volatile("ldmatrix.sync.aligned.m8n8.x4.shared.b16 {%0,%1,%2,%3}, [%4];"
    : "=r"(f[0]),"=r"(f[1]),"=r"(f[2]),"=r"(f[3]) : "r"(a));
}
__device__ __forceinline__ void ldsm2t(uint32_t* f, uint32_t a) {
  asm volatile("ldmatrix.sync.aligned.m8n8.x2.trans.shared.b16 {%0,%1}, [%2];"
    : "=r"(f[0]),"=r"(f[1]) : "r"(a));
}
__device__ __forceinline__ void mma16816(float* d, const uint32_t* a, const uint32_t* b) {
  asm volatile("mma.sync.aligned.m16n8k16.row.col.f32.bf16.bf16.f32 "
    "{%0,%1,%2,%3}, {%4,%5,%6,%7}, {%8,%9}, {%0,%1,%2,%3};"
    : "+f"(d[0]),"+f"(d[1]),"+f"(d[2]),"+f"(d[3])
    : "r"(a[0]),"r"(a[1]),"r"(a[2]),"r"(a[3]), "r"(b[0]),"r"(b[1]));
}
// A tile byte offset: row m, col k. 256B rows, 16B chunks XOR-swizzled by m&7.
__device__ __forceinline__ uint32_t swzA(int m, int k) {
  return (uint32_t)(m*256 + ((((k>>3) ^ (m&7))<<4) | ((k&7)*2)));
}
__device__ __forceinline__ ushort bf16u(float v) {
  return __bfloat16_as_ushort(__float2bfloat16(v));
}

__global__ __launch_bounds__(NTH, 1)
void rgat_hmma_kernel(const float* __restrict__ x,
                      const float* __restrict__ ln_gamma,
                      const float* __restrict__ ln_beta,
                      const float* __restrict__ alpha,
                      const float* __restrict__ Wl,
                      const float* __restrict__ bl,
                      const float* __restrict__ Wr,
                      const float* __restrict__ br,
                      const float* __restrict__ att,
                      const float* __restrict__ bias,
                      float* __restrict__ out)
{
  extern __shared__ char raw[];
  uintptr_t pa = ((uintptr_t)raw + 1023) & ~(uintptr_t)1023;
  Smem& s = *reinterpret_cast<Smem*>(pa);

  char* Ah_base = s.uni;
  char* Al_base = s.uni + MPAD*C*2;                    // +20480
  float (*xrT)[MPADT] = reinterpret_cast<float (*)[MPADT]>(s.uni);

  const int t    = threadIdx.x;
  const int warp = t >> 5;
  const int lane = t & 31;
  const int node0 = blockIdx.x * MROWS;
  const float* xblk = x + (size_t)node0 * C;

  // ---- prologue: zero A union, W tiles hi/lo swizzled, vectors ----
  for (int i = t; i < AUNION/4; i += NTH)
    reinterpret_cast<uint32_t*>(s.uni)[i] = 0u;
  for (int i = t; i < C*C/4; i += NTH) {
    int k = i >> 5, n4 = (i & 31) * 4;
    float4 vl = reinterpret_cast<const float4*>(Wl)[i];
    float4 vr = reinterpret_cast<const float4*>(Wr)[i];
    uint32_t off = (uint32_t)(k*256 + ((((n4>>3) ^ (k&7))<<4) | ((n4&7)*2)));
    ushort h0 = bf16u(vl.x), h1 = bf16u(vl.y), h2 = bf16u(vl.z), h3 = bf16u(vl.w);
    uint2 hp = make_uint2((uint32_t)h0 | ((uint32_t)h1 << 16),
                          (uint32_t)h2 | ((uint32_t)h3 << 16));
    uint2 lp = make_uint2(
      (uint32_t)bf16u(vl.x - __bfloat162float(__ushort_as_bfloat16(h0))) |
      ((uint32_t)bf16u(vl.y - __bfloat162float(__ushort_as_bfloat16(h1))) << 16),
      (uint32_t)bf16u(vl.z - __bfloat162float(__ushort_as_bfloat16(h2))) |
      ((uint32_t)bf16u(vl.w - __bfloat162float(__ushort_as_bfloat16(h3))) << 16));
    *reinterpret_cast<uint2*>(reinterpret_cast<char*>(s.Wlh) + off) = hp;
    *reinterpret_cast<uint2*>(reinterpret_cast<char*>(s.Wll) + off) = lp;
    h0 = bf16u(vr.x); h1 = bf16u(vr.y); h2 = bf16u(vr.z); h3 = bf16u(vr.w);
    hp = make_uint2((uint32_t)h0 | ((uint32_t)h1 << 16),
                    (uint32_t)h2 | ((uint32_t)h3 << 16));
    lp = make_uint2(
      (uint32_t)bf16u(vr.x - __bfloat162float(__ushort_as_bfloat16(h0))) |
      ((uint32_t)bf16u(vr.y - __bfloat162float(__ushort_as_bfloat16(h1))) << 16),
      (uint32_t)bf16u(vr.z - __bfloat162float(__ushort_as_bfloat16(h2))) |
      ((uint32_t)bf16u(vr.w - __bfloat162float(__ushort_as_bfloat16(h3))) << 16));
    *reinterpret_cast<uint2*>(reinterpret_cast<char*>(s.Wrh) + off) = hp;
    *reinterpret_cast<uint2*>(reinterpret_cast<char*>(s.Wrl) + off) = lp;
  }
  for (int i = t; i < C; i += NTH) {
    s.bl[i] = bl[i]; s.br[i] = br[i]; s.att[i] = att[i]; s.bias[i] = bias[i];
  }
  const float sg  = 1.0f / (1.0f + __expf(-alpha[0]));
  const float oms = 1.0f - sg;
  __syncthreads();   // zero-fill of union must complete before LN writes

  // ---- LayerNorm -> Ah/Al (hi/lo bf16) ----
  for (int r = warp; r < MROWS; r += 16) {
    float v0 = xblk[r*C + lane],      v1 = xblk[r*C + lane + 32];
    float v2 = xblk[r*C + lane + 64], v3 = xblk[r*C + lane + 96];
    float sum = v0+v1+v2+v3, sq = v0*v0+v1*v1+v2*v2+v3*v3;
    #pragma unroll
    for (int o = 16; o > 0; o >>= 1) {
      sum += __shfl_xor_sync(0xffffffffu, sum, o);
      sq  += __shfl_xor_sync(0xffffffffu, sq,  o);
    }
    float mu = sum * (1.0f/C);
    float inv = rsqrtf(sq * (1.0f/C) - mu*mu + 1e-5f);
    #pragma unroll
    for (int q = 0; q < 4; ++q) {
      int cc = lane + 32*q;
      float vv = (q==0?v0:q==1?v1:q==2?v2:v3);
      float hval = (vv-mu)*inv*ln_gamma[cc] + ln_beta[cc];
      ushort hi = bf16u(hval);
      *reinterpret_cast<ushort*>(Ah_base + swzA(r, cc)) = hi;
      *reinterpret_cast<ushort*>(Al_base + swzA(r, cc)) =
          bf16u(hval - __bfloat162float(__ushort_as_bfloat16(hi)));
    }
  }

  const uint32_t aAh  = smem_u32(Ah_base), aAl  = smem_u32(Al_base);
  const uint32_t aWlh = smem_u32(s.Wlh), aWll = smem_u32(s.Wll);
  const uint32_t aWrh = smem_u32(s.Wrh), aWrl = smem_u32(s.Wrl);
  // lane decomposition for ldmatrix addressing
  const int rA = lane & 7;
  const int rowOffA = ((lane>>3)&1)*8 + rA;   // matrix row offset within m16
  const int chOffA  = (lane>>4);              // k-chunk offset (0/1)
  const int rB  = lane & 7;
  const int miB = (lane>>3)&1;
  const int n0w = warp * 8;                   // this warp's 8 output columns
  const int eM = lane >> 2;                   // epilogue lane mapping
  const int eN = 2*(lane & 3);

  #pragma unroll 1
  for (int layer = 0; layer < 4; ++layer) {
    __syncthreads();   // Ah/Al ready (LN or previous aggregation)

    float accL[NMT][4];
    float accR[NMT][4];
    #pragma unroll
    for (int mt = 0; mt < NMT; ++mt)
      #pragma unroll
      for (int q = 0; q < 4; ++q) { accL[mt][q] = 0.f; accR[mt][q] = 0.f; }

    #pragma unroll
    for (int ks = 0; ks < 8; ++ks) {
      uint32_t fAh[NMT][4], fAl[NMT][4];
      #pragma unroll
      for (int mt = 0; mt < NMT; ++mt) {
        uint32_t ar = (uint32_t)((mt*16 + rowOffA)*256 + (((2*ks + chOffA) ^ rA)<<4));
        ldsm4(fAh[mt], aAh + ar);
        ldsm4(fAl[mt], aAl + ar);
      }
      uint32_t boff = (uint32_t)((ks*16 + miB*8 + rB)*256 + (((n0w>>3) ^ rB)<<4));
      uint32_t bh[2], blo[2];
      ldsm2t(bh,  aWlh + boff);
      ldsm2t(blo, aWll + boff);
      #pragma unroll
      for (int mt = 0; mt < NMT; ++mt) {
        mma16816(accL[mt], fAh[mt], bh);
        mma16816(accL[mt], fAl[mt], bh);
        mma16816(accL[mt], fAh[mt], blo);
      }
      ldsm2t(bh,  aWrh + boff);
      ldsm2t(blo, aWrl + boff);
      #pragma unroll
      for (int mt = 0; mt < NMT; ++mt) {
        mma16816(accR[mt], fAh[mt], bh);
        mma16816(accR[mt], fAl[mt], bh);
        mma16816(accR[mt], fAh[mt], blo);
      }
    }
    __syncthreads();   // all GEMM reads of Ah/Al done before xrT overwrites them

    // ---- epilogue: fragments -> xlT / xrT-in-union (+bias) ----
    {
      int n0 = n0w + eN;
      float b0 = s.bl[n0], b1 = s.bl[n0+1];
      float c0 = s.br[n0], c1 = s.br[n0+1];
      #pragma unroll
      for (int mt = 0; mt < NMT; ++mt) {
        int m0 = mt*16 + eM;
        if (m0 < MROWS) {
          s.xlT[n0  ][m0] = accL[mt][0] + b0;
          s.xlT[n0+1][m0] = accL[mt][1] + b1;
          xrT[n0  ][m0] = accR[mt][0] + c0;
          xrT[n0+1][m0] = accR[mt][1] + c1;
        }
        if (m0+8 < MROWS) {
          s.xlT[n0  ][m0+8] = accL[mt][2] + b0;
          s.xlT[n0+1][m0+8] = accL[mt][3] + b1;
          xrT[n0  ][m0+8] = accR[mt][2] + c0;
          xrT[n0+1][m0+8] = accR[mt][3] + c1;
        }
      }
    }
    __syncthreads();

    // ---- edge logits over UNIQUE edges: 16 warps * 8 = 128 ----
    #pragma unroll
    for (int i = 0; i < 8; ++i) {
      int eg = warp + 16*i;
      int g = eg >> 5, e = eg & 31;
      int gs = g*J + c_esrc[e];
      int gd = g*J + c_edst[e];
      float acc = 0.0f;
      #pragma unroll
      for (int q = 0; q < 4; ++q) {
        int cc = lane + 32*q;
        float v = s.xlT[cc][gs] + xrT[cc][gd];
        v = (v > 0.0f) ? v : 0.2f*v;
        acc += s.att[cc]*v;
      }
      #pragma unroll
      for (int o = 16; o > 0; o >>= 1)
        acc += __shfl_xor_sync(0xffffffffu, acc, o);
      if (lane == 0) s.logit[eg] = acc;
    }
    __syncthreads();

    // ---- segment softmax over unique incoming edges ----
    if (t < MROWS) {
      int g = t / J, n = t - (t / J) * J;
      const float* lg = &s.logit[g*NEU];
      float m = -1e30f;
      #pragma unroll
      for (int e = 0; e < NEU; ++e) if (EDST[e] == n) m = fmaxf(m, lg[e]);
      float d = 0.0f;
      #pragma unroll
      for (int e = 0; e < NEU; ++e) if (EDST[e] == n) d += __expf(lg[e] - m);
      s.mx[t] = m; s.den[t] = d;
    }
    __syncthreads();
    if (t < GPB*NEU) {
      int g = t >> 5, e = t & 31;
      int dn = g*J + c_edst[e];
      s.aw[t] = __expf(s.logit[t] - s.mx[dn]) / s.den[dn];
    }
    __syncthreads();

    // ---- aggregation over unique edges + gate; layer3 -> out = x + h ----
    {
      int g = t >> 7, cc = t & 127;
      float acc[J];
      #pragma unroll
      for (int n = 0; n < J; ++n) acc[n] = s.bias[cc];
      const float* ag = &s.aw[g*NEU];
      #pragma unroll
      for (int e = 0; e < NEU; ++e)
        acc[EDST[e]] += ag[e] * s.xlT[cc][g*J + ESRC[e]];
      #pragma unroll
      for (int n = 0; n < J; ++n) {
        int r = g*J + n;
        float v = acc[n];
        float xv = xblk[r*C + cc];
        if (layer > 0) v = oms*v + sg*xv;
        if (layer < 3) {
          ushort hi = bf16u(v);
          *reinterpret_cast<ushort*>(Ah_base + swzA(r, cc)) = hi;
          *reinterpret_cast<ushort*>(Al_base + swzA(r, cc)) =
              bf16u(v - __bfloat162float(__ushort_as_bfloat16(hi)));
        } else {
          out[(size_t)(node0 + r)*C + cc] = xv + v;
        }
      }
    }
  }
}

extern "C" void kernel_launch(void* const* d_in, const int* in_sizes, int n_in,
                              void* d_out, int out_size)
{
  const float* x        = (const float*)d_in[0];
  const float* ln_gamma = (const float*)d_in[1];
  const float* ln_beta  = (const float*)d_in[2];
  const float* alpha    = (const float*)d_in[3];
  const float* Wl       = (const float*)d_in[4];
  const float* bl       = (const float*)d_in[5];
  const float* Wr       = (const float*)d_in[6];
  const float* br       = (const float*)d_in[7];
  const float* att      = (const float*)d_in[8];
  const float* bias     = (const float*)d_in[9];
  (void)in_sizes; (void)n_in; (void)out_size;

  int smem = (int)sizeof(Smem) + 1024;
  (void)cudaFuncSetAttribute(rgat_hmma_kernel,
                             cudaFuncAttributeMaxDynamicSharedMemorySize, smem);
  rgat_hmma_kernel<<<NBLOCKS, NTH, smem>>>(
      x, ln_gamma, ln_beta, alpha, Wl, bl, Wr, br, att, bias, (float*)d_out);
}

// round 17
// speedup vs baseline: 1.5929x; 1.0299x over previous
#include <cuda_runtime.h>
#include <cuda_bf16.h>
#include <math.h>
#include <stdint.h>

// RGAT: 4x GATv2 over 15552 independent 17-node graphs, C=128.
// R17 = R16 + persistent blocks: 148 resident blocks load/split W ONCE and
// stride over graph batches (amortizes the ~7k-cycle weight prologue 26x).
// Per-batch body identical to R16 (unique-edge dedup, HMMA split hi/lo GEMM).

namespace {
constexpr int J   = 17;
constexpr int C   = 128;
constexpr int GPB = 4;
constexpr int MROWS = GPB * J;           // 68
constexpr int MPAD  = 80;                // MMA M (5 m-tiles)
constexpr int NMT = MPAD / 16;           // 5
constexpr int NEU = 32;                  // unique directed edges per graph
constexpr int NTH = 512;
constexpr int NGRAPHS = 15552;
constexpr int NBATCH = NGRAPHS / GPB;    // 3888 batches
constexpr int GRID = 148;                // persistent blocks (1 per SM)
constexpr int MPADT = 69;                // xlT/xrT row stride (69 mod 32 = 5)
constexpr int AUNION = 48 * 1024;        // union: Ah(20480)+Al(20480) | xrT(35328)
}

// 32 unique directed edges (the base list; it is closed under reversal).
__device__ constexpr int ESRC[NEU] = {
  0,0,0,1,1,2,2,3,4,4,5,5,6,7,7,8,8,8,8,9,9,10,11,11,12,12,13,14,14,15,15,16
};
__device__ constexpr int EDST[NEU] = {
  1,4,7,0,2,1,3,2,0,5,4,6,5,0,8,7,9,11,14,8,10,9,8,12,11,13,12,8,15,14,16,15
};
__device__ __constant__ int c_esrc[NEU] = {
  0,0,0,1,1,2,2,3,4,4,5,5,6,7,7,8,8,8,8,9,9,10,11,11,12,12,13,14,14,15,15,16
};
__device__ __constant__ int c_edst[NEU] = {
  1,4,7,0,2,1,3,2,0,5,4,6,5,0,8,7,9,11,14,8,10,9,8,12,11,13,12,8,15,14,16,15
};

struct Smem {
  __nv_bfloat16 Wlh[C*C];   // [k][n] swizzled, 32 KB each
  __nv_bfloat16 Wll[C*C];
  __nv_bfloat16 Wrh[C*C];
  __nv_bfloat16 Wrl[C*C];
  char uni[AUNION];         // Ah @ +0 (20480), Al @ +20480  |  xrT @ +0 (35328)
  float xlT[C][MPADT];      // 35328
  float bl[C], br[C], att[C], bias[C];
  float logit[GPB*NEU], aw[GPB*NEU];
  float mx[MROWS], den[MROWS];
};

// ---------------- helpers ----------------
__device__ __forceinline__ uint32_t smem_u32(const void* p) {
  uint32_t a;
  asm("{ .reg .u64 t; cvta.to.shared.u64 t, %1; cvt.u32.u64 %0, t; }" : "=r"(a) : "l"(p));
  return a;
}
__device__ __forceinline__ void ldsm4(uint32_t* f, uint32_t a) {
  asm volatile("ldmatrix.sync.aligned.m8n8.x4.shared.b16 {%0,%1,%2,%3}, [%4];"
    : "=r"(f[0]),"=r"(f[1]),"=r"(f[2]),"=r"(f[3]) : "r"(a));
}
__device__ __forceinline__ void ldsm2t(uint32_t* f, uint32_t a) {
  asm volatile("ldmatrix.sync.aligned.m8n8.x2.trans.shared.b16 {%0,%1}, [%2];"
    : "=r"(f[0]),"=r"(f[1]) : "r"(a));
}
__device__ __forceinline__ void mma16816(float* d, const uint32_t* a, const uint32_t* b) {
  asm volatile("mma.sync.aligned.m16n8k16.row.col.f32.bf16.bf16.f32 "
    "{%0,%1,%2,%3}, {%4,%5,%6,%7}, {%8,%9}, {%0,%1,%2,%3};"
    : "+f"(d[0]),"+f"(d[1]),"+f"(d[2]),"+f"(d[3])
    : "r"(a[0]),"r"(a[1]),"r"(a[2]),"r"(a[3]), "r"(b[0]),"r"(b[1]));
}
// A tile byte offset: row m, col k. 256B rows, 16B chunks XOR-swizzled by m&7.
__device__ __forceinline__ uint32_t swzA(int m, int k) {
  return (uint32_t)(m*256 + ((((k>>3) ^ (m&7))<<4) | ((k&7)*2)));
}
__device__ __forceinline__ ushort bf16u(float v) {
  return __bfloat16_as_ushort(__float2bfloat16(v));
}

__global__ __launch_bounds__(NTH, 1)
void rgat_hmma_kernel(const float* __restrict__ x,
                      const float* __restrict__ ln_gamma,
                      const float* __restrict__ ln_beta,
                      const float* __restrict__ alpha,
                      const float* __restrict__ Wl,
                      const float* __restrict__ bl,
                      const float* __restrict__ Wr,
                      const float* __restrict__ br,
                      const float* __restrict__ att,
                      const float* __restrict__ bias,
                      float* __restrict__ out)
{
  extern __shared__ char raw[];
  uintptr_t pa = ((uintptr_t)raw + 1023) & ~(uintptr_t)1023;
  Smem& s = *reinterpret_cast<Smem*>(pa);

  char* Ah_base = s.uni;
  char* Al_base = s.uni + MPAD*C*2;                    // +20480
  float (*xrT)[MPADT] = reinterpret_cast<float (*)[MPADT]>(s.uni);

  const int t    = threadIdx.x;
  const int warp = t >> 5;
  const int lane = t & 31;

  // ---- one-time prologue: zero A union, W tiles hi/lo swizzled, vectors ----
  for (int i = t; i < AUNION/4; i += NTH)
    reinterpret_cast<uint32_t*>(s.uni)[i] = 0u;
  for (int i = t; i < C*C/4; i += NTH) {
    int k = i >> 5, n4 = (i & 31) * 4;
    float4 vl = reinterpret_cast<const float4*>(Wl)[i];
    float4 vr = reinterpret_cast<const float4*>(Wr)[i];
    uint32_t off = (uint32_t)(k*256 + ((((n4>>3) ^ (k&7))<<4) | ((n4&7)*2)));
    ushort h0 = bf16u(vl.x), h1 = bf16u(vl.y), h2 = bf16u(vl.z), h3 = bf16u(vl.w);
    uint2 hp = make_uint2((uint32_t)h0 | ((uint32_t)h1 << 16),
                          (uint32_t)h2 | ((uint32_t)h3 << 16));
    uint2 lp = make_uint2(
      (uint32_t)bf16u(vl.x - __bfloat162float(__ushort_as_bfloat16(h0))) |
      ((uint32_t)bf16u(vl.y - __bfloat162float(__ushort_as_bfloat16(h1))) << 16),
      (uint32_t)bf16u(vl.z - __bfloat162float(__ushort_as_bfloat16(h2))) |
      ((uint32_t)bf16u(vl.w - __bfloat162float(__ushort_as_bfloat16(h3))) << 16));
    *reinterpret_cast<uint2*>(reinterpret_cast<char*>(s.Wlh) + off) = hp;
    *reinterpret_cast<uint2*>(reinterpret_cast<char*>(s.Wll) + off) = lp;
    h0 = bf16u(vr.x); h1 = bf16u(vr.y); h2 = bf16u(vr.z); h3 = bf16u(vr.w);
    hp = make_uint2((uint32_t)h0 | ((uint32_t)h1 << 16),
                    (uint32_t)h2 | ((uint32_t)h3 << 16));
    lp = make_uint2(
      (uint32_t)bf16u(vr.x - __bfloat162float(__ushort_as_bfloat16(h0))) |
      ((uint32_t)bf16u(vr.y - __bfloat162float(__ushort_as_bfloat16(h1))) << 16),
      (uint32_t)bf16u(vr.z - __bfloat162float(__ushort_as_bfloat16(h2))) |
      ((uint32_t)bf16u(vr.w - __bfloat162float(__ushort_as_bfloat16(h3))) << 16));
    *reinterpret_cast<uint2*>(reinterpret_cast<char*>(s.Wrh) + off) = hp;
    *reinterpret_cast<uint2*>(reinterpret_cast<char*>(s.Wrl) + off) = lp;
  }
  for (int i = t; i < C; i += NTH) {
    s.bl[i] = bl[i]; s.br[i] = br[i]; s.att[i] = att[i]; s.bias[i] = bias[i];
  }
  const float sg  = 1.0f / (1.0f + __expf(-alpha[0]));
  const float oms = 1.0f - sg;

  const uint32_t aAh  = smem_u32(Ah_base), aAl  = smem_u32(Al_base);
  const uint32_t aWlh = smem_u32(s.Wlh), aWll = smem_u32(s.Wll);
  const uint32_t aWrh = smem_u32(s.Wrh), aWrl = smem_u32(s.Wrl);
  // lane decomposition for ldmatrix addressing
  const int rA = lane & 7;
  const int rowOffA = ((lane>>3)&1)*8 + rA;   // matrix row offset within m16
  const int chOffA  = (lane>>4);              // k-chunk offset (0/1)
  const int rB  = lane & 7;
  const int miB = (lane>>3)&1;
  const int n0w = warp * 8;                   // this warp's 8 output columns
  const int eM = lane >> 2;                   // epilogue lane mapping
  const int eN = 2*(lane & 3);

  // ================= persistent batch loop =================
  for (int bb = blockIdx.x; bb < NBATCH; bb += GRID) {
    const int node0 = bb * MROWS;
    const float* xblk = x + (size_t)node0 * C;

    // previous batch's edge/agg reads of xrT (aliasing Ah/Al) must finish
    // before this batch's LN overwrites Ah/Al. Also covers the prologue on
    // the first iteration.
    __syncthreads();

    // ---- LayerNorm -> Ah/Al (hi/lo bf16) ----
    for (int r = warp; r < MROWS; r += 16) {
      float v0 = xblk[r*C + lane],      v1 = xblk[r*C + lane + 32];
      float v2 = xblk[r*C + lane + 64], v3 = xblk[r*C + lane + 96];
      float sum = v0+v1+v2+v3, sq = v0*v0+v1*v1+v2*v2+v3*v3;
      #pragma unroll
      for (int o = 16; o > 0; o >>= 1) {
        sum += __shfl_xor_sync(0xffffffffu, sum, o);
        sq  += __shfl_xor_sync(0xffffffffu, sq,  o);
      }
      float mu = sum * (1.0f/C);
      float inv = rsqrtf(sq * (1.0f/C) - mu*mu + 1e-5f);
      #pragma unroll
      for (int q = 0; q < 4; ++q) {
        int cc = lane + 32*q;
        float vv = (q==0?v0:q==1?v1:q==2?v2:v3);
        float hval = (vv-mu)*inv*ln_gamma[cc] + ln_beta[cc];
        ushort hi = bf16u(hval);
        *reinterpret_cast<ushort*>(Ah_base + swzA(r, cc)) = hi;
        *reinterpret_cast<ushort*>(Al_base + swzA(r, cc)) =
            bf16u(hval - __bfloat162float(__ushort_as_bfloat16(hi)));
      }
    }

    #pragma unroll 1
    for (int layer = 0; layer < 4; ++layer) {
      __syncthreads();   // Ah/Al ready (LN or previous aggregation)

      float accL[NMT][4];
      float accR[NMT][4];
      #pragma unroll
      for (int mt = 0; mt < NMT; ++mt)
        #pragma unroll
        for (int q = 0; q < 4; ++q) { accL[mt][q] = 0.f; accR[mt][q] = 0.f; }

      #pragma unroll
      for (int ks = 0; ks < 8; ++ks) {
        uint32_t fAh[NMT][4], fAl[NMT][4];
        #pragma unroll
        for (int mt = 0; mt < NMT; ++mt) {
          uint32_t ar = (uint32_t)((mt*16 + rowOffA)*256 + (((2*ks + chOffA) ^ rA)<<4));
          ldsm4(fAh[mt], aAh + ar);
          ldsm4(fAl[mt], aAl + ar);
        }
        uint32_t boff = (uint32_t)((ks*16 + miB*8 + rB)*256 + (((n0w>>3) ^ rB)<<4));
        uint32_t bh[2], blo[2];
        ldsm2t(bh,  aWlh + boff);
        ldsm2t(blo, aWll + boff);
        #pragma unroll
        for (int mt = 0; mt < NMT; ++mt) {
          mma16816(accL[mt], fAh[mt], bh);
          mma16816(accL[mt], fAl[mt], bh);
          mma16816(accL[mt], fAh[mt], blo);
        }
        ldsm2t(bh,  aWrh + boff);
        ldsm2t(blo, aWrl + boff);
        #pragma unroll
        for (int mt = 0; mt < NMT; ++mt) {
          mma16816(accR[mt], fAh[mt], bh);
          mma16816(accR[mt], fAl[mt], bh);
          mma16816(accR[mt], fAh[mt], blo);
        }
      }
      __syncthreads();   // all GEMM reads of Ah/Al done before xrT overwrites them

      // ---- epilogue: fragments -> xlT / xrT-in-union (+bias) ----
      {
        int n0 = n0w + eN;
        float b0 = s.bl[n0], b1 = s.bl[n0+1];
        float c0 = s.br[n0], c1 = s.br[n0+1];
        #pragma unroll
        for (int mt = 0; mt < NMT; ++mt) {
          int m0 = mt*16 + eM;
          if (m0 < MROWS) {
            s.xlT[n0  ][m0] = accL[mt][0] + b0;
            s.xlT[n0+1][m0] = accL[mt][1] + b1;
            xrT[n0  ][m0] = accR[mt][0] + c0;
            xrT[n0+1][m0] = accR[mt][1] + c1;
          }
          if (m0+8 < MROWS) {
            s.xlT[n0  ][m0+8] = accL[mt][2] + b0;
            s.xlT[n0+1][m0+8] = accL[mt][3] + b1;
            xrT[n0  ][m0+8] = accR[mt][2] + c0;
            xrT[n0+1][m0+8] = accR[mt][3] + c1;
          }
        }
      }
      __syncthreads();

      // ---- edge logits over UNIQUE edges: 16 warps * 8 = 128 ----
      #pragma unroll
      for (int i = 0; i < 8; ++i) {
        int eg = warp + 16*i;
        int g = eg >> 5, e = eg & 31;
        int gs = g*J + c_esrc[e];
        int gd = g*J + c_edst[e];
        float acc = 0.0f;
        #pragma unroll
        for (int q = 0; q < 4; ++q) {
          int cc = lane + 32*q;
          float v = s.xlT[cc][gs] + xrT[cc][gd];
          v = (v > 0.0f) ? v : 0.2f*v;
          acc += s.att[cc]*v;
        }
        #pragma unroll
        for (int o = 16; o > 0; o >>= 1)
          acc += __shfl_xor_sync(0xffffffffu, acc, o);
        if (lane == 0) s.logit[eg] = acc;
      }
      __syncthreads();

      // ---- segment softmax over unique incoming edges ----
      if (t < MROWS) {
        int g = t / J, n = t - (t / J) * J;
        const float* lg = &s.logit[g*NEU];
        float m = -1e30f;
        #pragma unroll
        for (int e = 0; e < NEU; ++e) if (EDST[e] == n) m = fmaxf(m, lg[e]);
        float d = 0.0f;
        #pragma unroll
        for (int e = 0; e < NEU; ++e) if (EDST[e] == n) d += __expf(lg[e] - m);
        s.mx[t] = m; s.den[t] = d;
      }
      __syncthreads();
      if (t < GPB*NEU) {
        int g = t >> 5, e = t & 31;
        int dn = g*J + c_edst[e];
        s.aw[t] = __expf(s.logit[t] - s.mx[dn]) / s.den[dn];
      }
      __syncthreads();

      // ---- aggregation over unique edges + gate; layer3 -> out = x + h ----
      {
        int g = t >> 7, cc = t & 127;
        float acc[J];
        #pragma unroll
        for (int n = 0; n < J; ++n) acc[n] = s.bias[cc];
        const float* ag = &s.aw[g*NEU];
        #pragma unroll
        for (int e = 0; e < NEU; ++e)
          acc[EDST[e]] += ag[e] * s.xlT[cc][g*J + ESRC[e]];
        #pragma unroll
        for (int n = 0; n < J; ++n) {
          int r = g*J + n;
          float v = acc[n];
          float xv = xblk[r*C + cc];
          if (layer > 0) v = oms*v + sg*xv;
          if (layer < 3) {
            ushort hi = bf16u(v);
            *reinterpret_cast<ushort*>(Ah_base + swzA(r, cc)) = hi;
            *reinterpret_cast<ushort*>(Al_base + swzA(r, cc)) =
                bf16u(v - __bfloat162float(__ushort_as_bfloat16(hi)));
          } else {
            out[(size_t)(node0 + r)*C + cc] = xv + v;
          }
        }
      }
    }
  }
}

extern "C" void kernel_launch(void* const* d_in, const int* in_sizes, int n_in,
                              void* d_out, int out_size)
{
  const float* x        = (const float*)d_in[0];
  const float* ln_gamma = (const float*)d_in[1];
  const float* ln_beta  = (const float*)d_in[2];
  const float* alpha    = (const float*)d_in[3];
  const float* Wl       = (const float*)d_in[4];
  const float* bl       = (const float*)d_in[5];
  const float* Wr       = (const float*)d_in[6];
  const float* br       = (const float*)d_in[7];
  const float* att      = (const float*)d_in[8];
  const float* bias     = (const float*)d_in[9];
  (void)in_sizes; (void)n_in; (void)out_size;

  int smem = (int)sizeof(Smem) + 1024;
  (void)cudaFuncSetAttribute(rgat_hmma_kernel,
                             cudaFuncAttributeMaxDynamicSharedMemorySize, smem);
  rgat_hmma_kernel<<<GRID, NTH, smem>>>(
      x, ln_gamma, ln_beta, alpha, Wl, bl, Wr, br, att, bias, (float*)d_out);
}